// round 15
// baseline (speedup 1.0000x reference)
#include <cuda_runtime.h>
#include <cuda_fp16.h>

// Problem constants
#define T_SEQ   4096
#define D_MODEL 512
#define N_HEADS 8
#define D_K     64
#define BATCH   2
#define BH      (BATCH * N_HEADS)       // 16
#define M_ROWS  (BATCH * T_SEQ)         // 8192
#define NTILES  (T_SEQ / 64)            // 64 key tiles

// Q is pre-scaled by 0.125 * log2(e) so softmax runs in base-2 domain.
#define QSCALE  (0.125f * 1.44269504088896f)

// f16 intermediates (16B aligned for uint4 access)
__device__ __align__(16) __half g_xh[(size_t)M_ROWS * D_MODEL];    // x f16
__device__ __align__(16) __half g_wq[(size_t)D_MODEL * D_MODEL];
__device__ __align__(16) __half g_wk[(size_t)D_MODEL * D_MODEL];
__device__ __align__(16) __half g_wv[(size_t)D_MODEL * D_MODEL];
__device__ __align__(16) __half g_wo[(size_t)D_MODEL * D_MODEL];
__device__ __align__(16) __half g_qh[(size_t)BH * T_SEQ * D_K];    // [bh][t][64] (pre-scaled)
__device__ __align__(16) __half g_kh[(size_t)BH * T_SEQ * D_K];
__device__ __align__(16) __half g_vh[(size_t)BH * T_SEQ * D_K];
__device__ __align__(16) __half g_oh[(size_t)M_ROWS * D_MODEL];    // attention out f16

// ===========================================================================
// Small helpers
// ===========================================================================
__device__ __forceinline__ unsigned smem_u32(const void* p) {
    unsigned a;
    asm("{ .reg .u64 t; cvta.to.shared.u64 t, %1; cvt.u32.u64 %0, t; }" : "=r"(a) : "l"(p));
    return a;
}
__device__ __forceinline__ float fast_exp2(float x) {
    float y;
    asm("ex2.approx.ftz.f32 %0, %1;" : "=f"(y) : "f"(x));
    return y;
}
// Row-major [row][64 halfs] tile with XOR swizzle on 16B chunks:
// byte offset of (row, chunk) = row*128 + (chunk ^ (row&7))*16
__device__ __forceinline__ unsigned swz(int row, int ch) {
    return (unsigned)(row * 128 + ((ch ^ (row & 7)) << 4));
}
__device__ __forceinline__ void ldm_x4(unsigned addr, unsigned& r0, unsigned& r1,
                                       unsigned& r2, unsigned& r3) {
    asm volatile("ldmatrix.sync.aligned.m8n8.x4.shared.b16 {%0,%1,%2,%3}, [%4];"
                 : "=r"(r0), "=r"(r1), "=r"(r2), "=r"(r3) : "r"(addr));
}
__device__ __forceinline__ void ldm_x4_t(unsigned addr, unsigned& r0, unsigned& r1,
                                         unsigned& r2, unsigned& r3) {
    asm volatile("ldmatrix.sync.aligned.m8n8.x4.trans.shared.b16 {%0,%1,%2,%3}, [%4];"
                 : "=r"(r0), "=r"(r1), "=r"(r2), "=r"(r3) : "r"(addr));
}
__device__ __forceinline__ void mma16816(float* c, const unsigned* a,
                                         unsigned b0, unsigned b1) {
    asm volatile(
        "mma.sync.aligned.m16n8k16.row.col.f32.f16.f16.f32 "
        "{%0,%1,%2,%3}, {%4,%5,%6,%7}, {%8,%9}, {%0,%1,%2,%3};"
        : "+f"(c[0]), "+f"(c[1]), "+f"(c[2]), "+f"(c[3])
        : "r"(a[0]), "r"(a[1]), "r"(a[2]), "r"(a[3]), "r"(b0), "r"(b1));
}
__device__ __forceinline__ void cp_async16(unsigned dst, const void* src) {
    asm volatile("cp.async.cg.shared.global [%0], [%1], 16;" :: "r"(dst), "l"(src));
}
#define CP_COMMIT()  asm volatile("cp.async.commit_group;" ::: "memory")
#define CP_WAIT(n)   asm volatile("cp.async.wait_group %0;" :: "n"(n) : "memory")

// ===========================================================================
// fp32 -> f16 converts.
// ===========================================================================
__global__ __launch_bounds__(256)
void f2h_x_kernel(const float* __restrict__ src, int n4)
{
    for (int i = blockIdx.x * blockDim.x + threadIdx.x; i < n4;
         i += gridDim.x * blockDim.x) {
        float4 v = *(const float4*)(src + 4 * (size_t)i);
        __half2 lo = __floats2half2_rn(v.x, v.y);
        __half2 hi = __floats2half2_rn(v.z, v.w);
        uint2 pk;
        pk.x = *reinterpret_cast<unsigned*>(&lo);
        pk.y = *reinterpret_cast<unsigned*>(&hi);
        *(uint2*)(g_xh + 4 * (size_t)i) = pk;
    }
}
__global__ __launch_bounds__(256)
void f2h_w_kernel(const float* __restrict__ wq, const float* __restrict__ wk,
                  const float* __restrict__ wv, const float* __restrict__ wo)
{
    const int sel = blockIdx.y;
    const float* src = (sel == 0) ? wq : (sel == 1) ? wk : (sel == 2) ? wv : wo;
    __half* dst = (sel == 0) ? g_wq : (sel == 1) ? g_wk : (sel == 2) ? g_wv : g_wo;
    const int n4 = (D_MODEL * D_MODEL) / 4;
    for (int i = blockIdx.x * blockDim.x + threadIdx.x; i < n4;
         i += gridDim.x * blockDim.x) {
        float4 v = *(const float4*)(src + 4 * (size_t)i);
        __half2 lo = __floats2half2_rn(v.x, v.y);
        __half2 hi = __floats2half2_rn(v.z, v.w);
        uint2 pk;
        pk.x = *reinterpret_cast<unsigned*>(&lo);
        pk.y = *reinterpret_cast<unsigned*>(&hi);
        *(uint2*)(dst + 4 * (size_t)i) = pk;
    }
}

// ===========================================================================
// f16 tensor-core GEMM body: C[m,n] = sum_k A[m,k]*W[n,k], fp32 accum.
// CTA tile 128m x 64n, K-chunks of 64, 4 warps.
// ===========================================================================
__device__ __forceinline__ void gemm_body(const __half* __restrict__ A,
                                          const __half* __restrict__ W,
                                          int m0, int n0,
                                          __half (*sA)[128 * 64], __half (*sB)[64 * 64],
                                          float c[2][8][4])
{
    const int tid  = threadIdx.x;
    const int w    = tid >> 5;
    const int lane = tid & 31;
    const unsigned bA0 = smem_u32(sA[0]), bA1 = smem_u32(sA[1]);
    const unsigned bB0 = smem_u32(sB[0]), bB1 = smem_u32(sB[1]);
    const int arow = tid >> 3, ach = tid & 7;

#pragma unroll
    for (int i = 0; i < 8; i++) {
        int row = arow + 16 * i;
        *(uint4*)((char*)sA[0] + swz(row, ach)) =
            *(const uint4*)(A + (size_t)(m0 + row) * D_MODEL + ach * 8);
    }
#pragma unroll
    for (int i = 0; i < 4; i++) {
        int row = arow + 16 * i;
        *(uint4*)((char*)sB[0] + swz(row, ach)) =
            *(const uint4*)(W + (size_t)(n0 + row) * D_MODEL + ach * 8);
    }
    __syncthreads();

#pragma unroll
    for (int mt = 0; mt < 2; mt++)
#pragma unroll
        for (int n = 0; n < 8; n++)
#pragma unroll
            for (int cc = 0; cc < 4; cc++) c[mt][n][cc] = 0.0f;

    for (int kt = 0; kt < D_MODEL / 64; kt++) {
        const int cur = kt & 1;
        const unsigned cA = cur ? bA1 : bA0;
        const unsigned cB = cur ? bB1 : bB0;

        uint4 pA[8], pB[4];
        if (kt + 1 < D_MODEL / 64) {
            const __half* Ap = A + (size_t)(kt + 1) * 64;
            const __half* Wp = W + (size_t)(kt + 1) * 64;
#pragma unroll
            for (int i = 0; i < 8; i++) {
                int row = arow + 16 * i;
                pA[i] = *(const uint4*)(Ap + (size_t)(m0 + row) * D_MODEL + ach * 8);
            }
#pragma unroll
            for (int i = 0; i < 4; i++) {
                int row = arow + 16 * i;
                pB[i] = *(const uint4*)(Wp + (size_t)(n0 + row) * D_MODEL + ach * 8);
            }
        }

#pragma unroll
        for (int kk = 0; kk < 4; kk++) {
            unsigned a[2][4];
#pragma unroll
            for (int mt = 0; mt < 2; mt++) {
                int row = 32 * w + 16 * mt + (lane & 15);
                int ch  = 2 * kk + (lane >> 4);
                ldm_x4(cA + swz(row, ch), a[mt][0], a[mt][1], a[mt][2], a[mt][3]);
            }
#pragma unroll
            for (int nt2 = 0; nt2 < 4; nt2++) {
                unsigned b0, b1, b2, b3;
                int row = nt2 * 16 + ((lane >> 4) << 3) + (lane & 7);
                int ch  = 2 * kk + ((lane >> 3) & 1);
                ldm_x4(cB + swz(row, ch), b0, b1, b2, b3);
#pragma unroll
                for (int mt = 0; mt < 2; mt++) {
                    mma16816(c[mt][2 * nt2 + 0], a[mt], b0, b1);
                    mma16816(c[mt][2 * nt2 + 1], a[mt], b2, b3);
                }
            }
        }

        if (kt + 1 < D_MODEL / 64) {
            __half* nA = (__half*)(cur ? (void*)sA[0] : (void*)sA[1]);
            __half* nB = (__half*)(cur ? (void*)sB[0] : (void*)sB[1]);
#pragma unroll
            for (int i = 0; i < 8; i++)
                *(uint4*)((char*)nA + swz(arow + 16 * i, ach)) = pA[i];
#pragma unroll
            for (int i = 0; i < 4; i++)
                *(uint4*)((char*)nB + swz(arow + 16 * i, ach)) = pB[i];
        }
        __syncthreads();
    }
}

// QKV projections fused: blockIdx.z = 0(Q)/1(K)/2(V).
__global__ __launch_bounds__(128)
void gemm_qkv_kernel(const float* __restrict__ bq, const float* __restrict__ bk,
                     const float* __restrict__ bv)
{
    __shared__ __half sA[2][128 * 64];
    __shared__ __half sB[2][64 * 64];

    const int z = blockIdx.z;
    const __half* W = (z == 0) ? g_wq : (z == 1) ? g_wk : g_wv;
    const float* bias = (z == 0) ? bq : (z == 1) ? bk : bv;
    __half* dst = (z == 0) ? g_qh : (z == 1) ? g_kh : g_vh;
    const float sc = (z == 0) ? QSCALE : 1.0f;

    const int n0 = blockIdx.x * 64;
    const int m0 = blockIdx.y * 128;
    const int h  = blockIdx.x;

    float c[2][8][4];
    gemm_body(g_xh, W, m0, n0, sA, sB, c);

    const int tid = threadIdx.x;
    const int w = tid >> 5, lane = tid & 31;
    const int gid = lane >> 2, tig = lane & 3;
#pragma unroll
    for (int mt = 0; mt < 2; mt++)
#pragma unroll
        for (int r01 = 0; r01 < 2; r01++) {
            int m = m0 + 32 * w + 16 * mt + gid + 8 * r01;
            int b = m >> 12;
            int t = m & (T_SEQ - 1);
            __half* op = &dst[(((size_t)(b * N_HEADS + h)) * T_SEQ + t) * D_K];
#pragma unroll
            for (int n = 0; n < 8; n++) {
                int d = n * 8 + 2 * tig;
                __half2 hv = __floats2half2_rn(
                    (c[mt][n][2 * r01 + 0] + bias[n0 + d]) * sc,
                    (c[mt][n][2 * r01 + 1] + bias[n0 + d + 1]) * sc);
                *(__half2*)(op + d) = hv;
            }
        }
}

// Output projection: A = g_oh, fp32 result to out.
__global__ __launch_bounds__(128)
void gemm_o_kernel(const float* __restrict__ bias, float* __restrict__ outf)
{
    __shared__ __half sA[2][128 * 64];
    __shared__ __half sB[2][64 * 64];

    const int n0 = blockIdx.x * 64;
    const int m0 = blockIdx.y * 128;

    float c[2][8][4];
    gemm_body(g_oh, g_wo, m0, n0, sA, sB, c);

    const int tid = threadIdx.x;
    const int w = tid >> 5, lane = tid & 31;
    const int gid = lane >> 2, tig = lane & 3;
#pragma unroll
    for (int mt = 0; mt < 2; mt++)
#pragma unroll
        for (int r01 = 0; r01 < 2; r01++) {
            int m = m0 + 32 * w + 16 * mt + gid + 8 * r01;
            float* op = &outf[(size_t)m * D_MODEL + n0];
#pragma unroll
            for (int n = 0; n < 8; n++) {
                int d = n * 8 + 2 * tig;
                float2 v;
                v.x = c[mt][n][2 * r01 + 0] + bias[n0 + d];
                v.y = c[mt][n][2 * r01 + 1] + bias[n0 + d + 1];
                *(float2*)(op + d) = v;
            }
        }
}

// ===========================================================================
// mma.sync f16 flash attention, v3 (occupancy build):
//  - CTA = 64 queries, 4 warps x 16 rows (halved per-warp state)
//  - __launch_bounds__(128, 3) -> 3 CTAs/SM = 12 warps/SM (was 8):
//    other warps' HMMAs cover each warp's softmax latency chain
//  - Q A-fragments in registers; cp.async 3-stage K/V pipeline (48 KB)
// ===========================================================================
__global__ __launch_bounds__(128, 3)
void attn_mma_kernel()
{
    __shared__ __half sKV[3][2][64 * 64];   // [stage][0=K,1=V][8KB]

    const int tid  = threadIdx.x;
    const int w    = tid >> 5;
    const int lane = tid & 31;
    const int gid  = lane >> 2;
    const int tig  = lane & 3;
    const int bh   = blockIdx.y;
    const int qt   = blockIdx.x;

    const __half* Qp = g_qh + (size_t)bh * T_SEQ * D_K + (size_t)qt * 64 * D_K;
    const __half* Kb = g_kh + (size_t)bh * T_SEQ * D_K;
    const __half* Vb = g_vh + (size_t)bh * T_SEQ * D_K;

    unsigned uK[3], uV[3];
#pragma unroll
    for (int st = 0; st < 3; st++) {
        uK[st] = smem_u32(sKV[st][0]);
        uV[st] = smem_u32(sKV[st][1]);
    }
    const int arow = tid >> 3, ach = tid & 7;

    // ---- Prologue: Q (64 rows) through stage-2 smem -> register A-frags ----
    {
        char* q2 = (char*)sKV[2];   // uses 8 KB of the 16 KB stage-2 region
#pragma unroll
        for (int i = 0; i < 4; i++) {
            int row = arow + 16 * i;
            *(uint4*)(q2 + swz(row, ach)) =
                *(const uint4*)(Qp + row * D_K + ach * 8);
        }
    }
    __syncthreads();
    unsigned qf[4][4];   // [kk][frag], warp rows 16w..16w+15
    {
        unsigned bQ = uK[2];
#pragma unroll
        for (int kk = 0; kk < 4; kk++) {
            int row = 16 * w + (lane & 15);
            int ch  = 2 * kk + (lane >> 4);
            ldm_x4(bQ + swz(row, ch), qf[kk][0], qf[kk][1], qf[kk][2], qf[kk][3]);
        }
    }
    // Stage 2 is first overwritten by the cp.async issued in iteration kt=0,
    // which is after a __syncthreads() — Q frags already in registers.

    // ---- Kick off pipeline: tiles 0 and 1 ----
#pragma unroll
    for (int p = 0; p < 2; p++) {
        const __half* Kp = Kb + (size_t)p * 64 * D_K;
        const __half* Vp = Vb + (size_t)p * 64 * D_K;
#pragma unroll
        for (int i = 0; i < 4; i++) {
            int row = arow + 16 * i;
            cp_async16(uK[p] + swz(row, ach), Kp + row * D_K + ach * 8);
            cp_async16(uV[p] + swz(row, ach), Vp + row * D_K + ach * 8);
        }
        CP_COMMIT();
    }

    float o[8][4];
#pragma unroll
    for (int n = 0; n < 8; n++)
#pragma unroll
        for (int cc = 0; cc < 4; cc++) o[n][cc] = 0.0f;
    float mrow[2] = {-1e30f, -1e30f};
    float lrow[2] = {0.0f, 0.0f};

    for (int kt = 0; kt < NTILES; kt++) {
        const int st = kt % 3;
        const unsigned cK = uK[st];
        const unsigned cV = uV[st];

        if (kt + 1 < NTILES) { CP_WAIT(1); } else { CP_WAIT(0); }
        __syncthreads();

        if (kt + 2 < NTILES) {
            const int st2 = (kt + 2) % 3;
            const __half* Kp = Kb + (size_t)(kt + 2) * 64 * D_K;
            const __half* Vp = Vb + (size_t)(kt + 2) * 64 * D_K;
#pragma unroll
            for (int i = 0; i < 4; i++) {
                int row = arow + 16 * i;
                cp_async16(uK[st2] + swz(row, ach), Kp + row * D_K + ach * 8);
                cp_async16(uV[st2] + swz(row, ach), Vp + row * D_K + ach * 8);
            }
            CP_COMMIT();
        }

        // ---- MMA1: S[16x64] = Q * K^T (Q frags from registers) ----
        float s[8][4];
#pragma unroll
        for (int n = 0; n < 8; n++)
#pragma unroll
            for (int cc = 0; cc < 4; cc++) s[n][cc] = 0.0f;

#pragma unroll
        for (int kk = 0; kk < 4; kk++) {
#pragma unroll
            for (int nt2 = 0; nt2 < 4; nt2++) {
                unsigned b0, b1, b2, b3;
                int row = nt2 * 16 + ((lane >> 4) << 3) + (lane & 7);
                int ch  = 2 * kk + ((lane >> 3) & 1);
                ldm_x4(cK + swz(row, ch), b0, b1, b2, b3);
                mma16816(s[2 * nt2 + 0], qf[kk], b0, b1);
                mma16816(s[2 * nt2 + 1], qf[kk], b2, b3);
            }
        }

        // ---- Online softmax (base-2; Q pre-scaled by 0.125*log2e) ----
        unsigned pa_lo[8], pa_hi[8];
        {
            float mx0 = -1e30f, mx1 = -1e30f;
#pragma unroll
            for (int n = 0; n < 8; n++) {
                mx0 = fmaxf(mx0, fmaxf(s[n][0], s[n][1]));
                mx1 = fmaxf(mx1, fmaxf(s[n][2], s[n][3]));
            }
            mx0 = fmaxf(mx0, __shfl_xor_sync(0xffffffffu, mx0, 1));
            mx0 = fmaxf(mx0, __shfl_xor_sync(0xffffffffu, mx0, 2));
            mx1 = fmaxf(mx1, __shfl_xor_sync(0xffffffffu, mx1, 1));
            mx1 = fmaxf(mx1, __shfl_xor_sync(0xffffffffu, mx1, 2));

            float m0n = fmaxf(mrow[0], mx0);
            float m1n = fmaxf(mrow[1], mx1);
            float c0 = fast_exp2(mrow[0] - m0n);
            float c1 = fast_exp2(mrow[1] - m1n);
            mrow[0] = m0n;
            mrow[1] = m1n;

            float sum0 = 0.0f, sum1 = 0.0f;
#pragma unroll
            for (int n = 0; n < 8; n++) {
                float p0 = fast_exp2(s[n][0] - m0n);
                float p1 = fast_exp2(s[n][1] - m0n);
                float p2 = fast_exp2(s[n][2] - m1n);
                float p3 = fast_exp2(s[n][3] - m1n);
                sum0 += p0 + p1;
                sum1 += p2 + p3;
                __half2 lo = __floats2half2_rn(p0, p1);
                __half2 hi = __floats2half2_rn(p2, p3);
                pa_lo[n] = *reinterpret_cast<unsigned*>(&lo);
                pa_hi[n] = *reinterpret_cast<unsigned*>(&hi);
            }
            sum0 += __shfl_xor_sync(0xffffffffu, sum0, 1);
            sum0 += __shfl_xor_sync(0xffffffffu, sum0, 2);
            sum1 += __shfl_xor_sync(0xffffffffu, sum1, 1);
            sum1 += __shfl_xor_sync(0xffffffffu, sum1, 2);
            lrow[0] = lrow[0] * c0 + sum0;
            lrow[1] = lrow[1] * c1 + sum1;

#pragma unroll
            for (int n = 0; n < 8; n++) {
                o[n][0] *= c0;
                o[n][1] *= c0;
                o[n][2] *= c1;
                o[n][3] *= c1;
            }
        }

        // ---- MMA2: O += P * V ----
#pragma unroll
        for (int kk = 0; kk < 4; kk++) {
            unsigned aP[4];
            aP[0] = pa_lo[2 * kk];
            aP[1] = pa_hi[2 * kk];
            aP[2] = pa_lo[2 * kk + 1];
            aP[3] = pa_hi[2 * kk + 1];
#pragma unroll
            for (int j2 = 0; j2 < 4; j2++) {
                unsigned b0, b1, b2, b3;
                int row = kk * 16 + (((lane >> 3) & 1) << 3) + (lane & 7);
                int ch  = 2 * j2 + (lane >> 4);
                ldm_x4_t(cV + swz(row, ch), b0, b1, b2, b3);
                mma16816(o[2 * j2 + 0], aP, b0, b1);
                mma16816(o[2 * j2 + 1], aP, b2, b3);
            }
        }
    }

    // ---- Epilogue: normalize, write f16 to g_oh[(b*T + t)*512 + h*64 + d] ----
    const int b = bh >> 3;
    const int h = bh & 7;
#pragma unroll
    for (int r01 = 0; r01 < 2; r01++) {
        int t = qt * 64 + 16 * w + gid + 8 * r01;
        float inv = 1.0f / lrow[r01];
        __half* op = &g_oh[((size_t)(b * T_SEQ + t)) * D_MODEL + h * D_K];
#pragma unroll
        for (int n = 0; n < 8; n++) {
            __half2 hv = __floats2half2_rn(o[n][2 * r01 + 0] * inv,
                                           o[n][2 * r01 + 1] * inv);
            *(__half2*)(op + n * 8 + 2 * tig) = hv;
        }
    }
}

// ===========================================================================
// Launch
// ===========================================================================
extern "C" void kernel_launch(void* const* d_in, const int* in_sizes, int n_in,
                              void* d_out, int out_size)
{
    const float* x  = (const float*)d_in[0];
    const float* Wq = (const float*)d_in[1];
    const float* bq = (const float*)d_in[2];
    const float* Wk = (const float*)d_in[3];
    const float* bk = (const float*)d_in[4];
    const float* Wv = (const float*)d_in[5];
    const float* bv = (const float*)d_in[6];
    const float* Wo = (const float*)d_in[7];
    const float* bo = (const float*)d_in[8];
    float* out = (float*)d_out;

    f2h_x_kernel<<<512, 256>>>(x, (M_ROWS * D_MODEL) / 4);
    f2h_w_kernel<<<dim3(64, 4, 1), 256>>>(Wq, Wk, Wv, Wo);

    dim3 blk(128, 1, 1);
    gemm_qkv_kernel<<<dim3(D_MODEL / 64, M_ROWS / 128, 3), blk>>>(bq, bk, bv);

    attn_mma_kernel<<<dim3(T_SEQ / 64, BH, 1), blk>>>();

    gemm_o_kernel<<<dim3(D_MODEL / 64, M_ROWS / 128, 1), blk>>>(bo, out);
}

// round 16
// speedup vs baseline: 1.0108x; 1.0108x over previous
#include <cuda_runtime.h>
#include <cuda_fp16.h>

// Problem constants
#define T_SEQ   4096
#define D_MODEL 512
#define N_HEADS 8
#define D_K     64
#define BATCH   2
#define BH      (BATCH * N_HEADS)       // 16
#define M_ROWS  (BATCH * T_SEQ)         // 8192
#define NTILES  (T_SEQ / 64)            // 64 key tiles

// Q is pre-scaled by 0.125 * log2(e) so softmax runs in base-2 domain.
#define QSCALE  (0.125f * 1.44269504088896f)

// f16 intermediates (16B aligned for uint4 access)
__device__ __align__(16) __half g_xh[(size_t)M_ROWS * D_MODEL];    // x f16
__device__ __align__(16) __half g_wq[(size_t)D_MODEL * D_MODEL];
__device__ __align__(16) __half g_wk[(size_t)D_MODEL * D_MODEL];
__device__ __align__(16) __half g_wv[(size_t)D_MODEL * D_MODEL];
__device__ __align__(16) __half g_wo[(size_t)D_MODEL * D_MODEL];
__device__ __align__(16) __half g_qh[(size_t)BH * T_SEQ * D_K];    // [bh][t][64] (pre-scaled)
__device__ __align__(16) __half g_kh[(size_t)BH * T_SEQ * D_K];
__device__ __align__(16) __half g_vh[(size_t)BH * T_SEQ * D_K];
__device__ __align__(16) __half g_oh[(size_t)M_ROWS * D_MODEL];    // attention out f16

// ===========================================================================
// Small helpers
// ===========================================================================
__device__ __forceinline__ unsigned smem_u32(const void* p) {
    unsigned a;
    asm("{ .reg .u64 t; cvta.to.shared.u64 t, %1; cvt.u32.u64 %0, t; }" : "=r"(a) : "l"(p));
    return a;
}
__device__ __forceinline__ float fast_exp2(float x) {
    float y;
    asm("ex2.approx.ftz.f32 %0, %1;" : "=f"(y) : "f"(x));
    return y;
}
// Row-major [row][64 halfs] tile with XOR swizzle on 16B chunks:
// byte offset of (row, chunk) = row*128 + (chunk ^ (row&7))*16
__device__ __forceinline__ unsigned swz(int row, int ch) {
    return (unsigned)(row * 128 + ((ch ^ (row & 7)) << 4));
}
__device__ __forceinline__ void ldm_x4(unsigned addr, unsigned& r0, unsigned& r1,
                                       unsigned& r2, unsigned& r3) {
    asm volatile("ldmatrix.sync.aligned.m8n8.x4.shared.b16 {%0,%1,%2,%3}, [%4];"
                 : "=r"(r0), "=r"(r1), "=r"(r2), "=r"(r3) : "r"(addr));
}
__device__ __forceinline__ void ldm_x4_t(unsigned addr, unsigned& r0, unsigned& r1,
                                         unsigned& r2, unsigned& r3) {
    asm volatile("ldmatrix.sync.aligned.m8n8.x4.trans.shared.b16 {%0,%1,%2,%3}, [%4];"
                 : "=r"(r0), "=r"(r1), "=r"(r2), "=r"(r3) : "r"(addr));
}
__device__ __forceinline__ void mma16816(float* c, const unsigned* a,
                                         unsigned b0, unsigned b1) {
    asm volatile(
        "mma.sync.aligned.m16n8k16.row.col.f32.f16.f16.f32 "
        "{%0,%1,%2,%3}, {%4,%5,%6,%7}, {%8,%9}, {%0,%1,%2,%3};"
        : "+f"(c[0]), "+f"(c[1]), "+f"(c[2]), "+f"(c[3])
        : "r"(a[0]), "r"(a[1]), "r"(a[2]), "r"(a[3]), "r"(b0), "r"(b1));
}
__device__ __forceinline__ void cp_async16(unsigned dst, const void* src) {
    asm volatile("cp.async.cg.shared.global [%0], [%1], 16;" :: "r"(dst), "l"(src));
}
#define CP_COMMIT()  asm volatile("cp.async.commit_group;" ::: "memory")
#define CP_WAIT(n)   asm volatile("cp.async.wait_group %0;" :: "n"(n) : "memory")

// ===========================================================================
// fp32 -> f16 converts.
// ===========================================================================
__global__ __launch_bounds__(256)
void f2h_x_kernel(const float* __restrict__ src, int n4)
{
    for (int i = blockIdx.x * blockDim.x + threadIdx.x; i < n4;
         i += gridDim.x * blockDim.x) {
        float4 v = *(const float4*)(src + 4 * (size_t)i);
        __half2 lo = __floats2half2_rn(v.x, v.y);
        __half2 hi = __floats2half2_rn(v.z, v.w);
        uint2 pk;
        pk.x = *reinterpret_cast<unsigned*>(&lo);
        pk.y = *reinterpret_cast<unsigned*>(&hi);
        *(uint2*)(g_xh + 4 * (size_t)i) = pk;
    }
}
__global__ __launch_bounds__(256)
void f2h_w_kernel(const float* __restrict__ wq, const float* __restrict__ wk,
                  const float* __restrict__ wv, const float* __restrict__ wo)
{
    const int sel = blockIdx.y;
    const float* src = (sel == 0) ? wq : (sel == 1) ? wk : (sel == 2) ? wv : wo;
    __half* dst = (sel == 0) ? g_wq : (sel == 1) ? g_wk : (sel == 2) ? g_wv : g_wo;
    const int n4 = (D_MODEL * D_MODEL) / 4;
    for (int i = blockIdx.x * blockDim.x + threadIdx.x; i < n4;
         i += gridDim.x * blockDim.x) {
        float4 v = *(const float4*)(src + 4 * (size_t)i);
        __half2 lo = __floats2half2_rn(v.x, v.y);
        __half2 hi = __floats2half2_rn(v.z, v.w);
        uint2 pk;
        pk.x = *reinterpret_cast<unsigned*>(&lo);
        pk.y = *reinterpret_cast<unsigned*>(&hi);
        *(uint2*)(dst + 4 * (size_t)i) = pk;
    }
}

// ===========================================================================
// f16 tensor-core GEMM body: C[m,n] = sum_k A[m,k]*W[n,k], fp32 accum.
// CTA tile 128m x 64n, K-chunks of 64, 4 warps.
// ===========================================================================
__device__ __forceinline__ void gemm_body(const __half* __restrict__ A,
                                          const __half* __restrict__ W,
                                          int m0, int n0,
                                          __half (*sA)[128 * 64], __half (*sB)[64 * 64],
                                          float c[2][8][4])
{
    const int tid  = threadIdx.x;
    const int w    = tid >> 5;
    const int lane = tid & 31;
    const unsigned bA0 = smem_u32(sA[0]), bA1 = smem_u32(sA[1]);
    const unsigned bB0 = smem_u32(sB[0]), bB1 = smem_u32(sB[1]);
    const int arow = tid >> 3, ach = tid & 7;

#pragma unroll
    for (int i = 0; i < 8; i++) {
        int row = arow + 16 * i;
        *(uint4*)((char*)sA[0] + swz(row, ach)) =
            *(const uint4*)(A + (size_t)(m0 + row) * D_MODEL + ach * 8);
    }
#pragma unroll
    for (int i = 0; i < 4; i++) {
        int row = arow + 16 * i;
        *(uint4*)((char*)sB[0] + swz(row, ach)) =
            *(const uint4*)(W + (size_t)(n0 + row) * D_MODEL + ach * 8);
    }
    __syncthreads();

#pragma unroll
    for (int mt = 0; mt < 2; mt++)
#pragma unroll
        for (int n = 0; n < 8; n++)
#pragma unroll
            for (int cc = 0; cc < 4; cc++) c[mt][n][cc] = 0.0f;

    for (int kt = 0; kt < D_MODEL / 64; kt++) {
        const int cur = kt & 1;
        const unsigned cA = cur ? bA1 : bA0;
        const unsigned cB = cur ? bB1 : bB0;

        uint4 pA[8], pB[4];
        if (kt + 1 < D_MODEL / 64) {
            const __half* Ap = A + (size_t)(kt + 1) * 64;
            const __half* Wp = W + (size_t)(kt + 1) * 64;
#pragma unroll
            for (int i = 0; i < 8; i++) {
                int row = arow + 16 * i;
                pA[i] = *(const uint4*)(Ap + (size_t)(m0 + row) * D_MODEL + ach * 8);
            }
#pragma unroll
            for (int i = 0; i < 4; i++) {
                int row = arow + 16 * i;
                pB[i] = *(const uint4*)(Wp + (size_t)(n0 + row) * D_MODEL + ach * 8);
            }
        }

#pragma unroll
        for (int kk = 0; kk < 4; kk++) {
            unsigned a[2][4];
#pragma unroll
            for (int mt = 0; mt < 2; mt++) {
                int row = 32 * w + 16 * mt + (lane & 15);
                int ch  = 2 * kk + (lane >> 4);
                ldm_x4(cA + swz(row, ch), a[mt][0], a[mt][1], a[mt][2], a[mt][3]);
            }
#pragma unroll
            for (int nt2 = 0; nt2 < 4; nt2++) {
                unsigned b0, b1, b2, b3;
                int row = nt2 * 16 + ((lane >> 4) << 3) + (lane & 7);
                int ch  = 2 * kk + ((lane >> 3) & 1);
                ldm_x4(cB + swz(row, ch), b0, b1, b2, b3);
#pragma unroll
                for (int mt = 0; mt < 2; mt++) {
                    mma16816(c[mt][2 * nt2 + 0], a[mt], b0, b1);
                    mma16816(c[mt][2 * nt2 + 1], a[mt], b2, b3);
                }
            }
        }

        if (kt + 1 < D_MODEL / 64) {
            __half* nA = (__half*)(cur ? (void*)sA[0] : (void*)sA[1]);
            __half* nB = (__half*)(cur ? (void*)sB[0] : (void*)sB[1]);
#pragma unroll
            for (int i = 0; i < 8; i++)
                *(uint4*)((char*)nA + swz(arow + 16 * i, ach)) = pA[i];
#pragma unroll
            for (int i = 0; i < 4; i++)
                *(uint4*)((char*)nB + swz(arow + 16 * i, ach)) = pB[i];
        }
        __syncthreads();
    }
}

// QKV projections fused: blockIdx.z = 0(Q)/1(K)/2(V).
__global__ __launch_bounds__(128)
void gemm_qkv_kernel(const float* __restrict__ bq, const float* __restrict__ bk,
                     const float* __restrict__ bv)
{
    __shared__ __half sA[2][128 * 64];
    __shared__ __half sB[2][64 * 64];

    const int z = blockIdx.z;
    const __half* W = (z == 0) ? g_wq : (z == 1) ? g_wk : g_wv;
    const float* bias = (z == 0) ? bq : (z == 1) ? bk : bv;
    __half* dst = (z == 0) ? g_qh : (z == 1) ? g_kh : g_vh;
    const float sc = (z == 0) ? QSCALE : 1.0f;

    const int n0 = blockIdx.x * 64;
    const int m0 = blockIdx.y * 128;
    const int h  = blockIdx.x;

    float c[2][8][4];
    gemm_body(g_xh, W, m0, n0, sA, sB, c);

    const int tid = threadIdx.x;
    const int w = tid >> 5, lane = tid & 31;
    const int gid = lane >> 2, tig = lane & 3;
#pragma unroll
    for (int mt = 0; mt < 2; mt++)
#pragma unroll
        for (int r01 = 0; r01 < 2; r01++) {
            int m = m0 + 32 * w + 16 * mt + gid + 8 * r01;
            int b = m >> 12;
            int t = m & (T_SEQ - 1);
            __half* op = &dst[(((size_t)(b * N_HEADS + h)) * T_SEQ + t) * D_K];
#pragma unroll
            for (int n = 0; n < 8; n++) {
                int d = n * 8 + 2 * tig;
                __half2 hv = __floats2half2_rn(
                    (c[mt][n][2 * r01 + 0] + bias[n0 + d]) * sc,
                    (c[mt][n][2 * r01 + 1] + bias[n0 + d + 1]) * sc);
                *(__half2*)(op + d) = hv;
            }
        }
}

// Output projection: A = g_oh, fp32 result to out.
__global__ __launch_bounds__(128)
void gemm_o_kernel(const float* __restrict__ bias, float* __restrict__ outf)
{
    __shared__ __half sA[2][128 * 64];
    __shared__ __half sB[2][64 * 64];

    const int n0 = blockIdx.x * 64;
    const int m0 = blockIdx.y * 128;

    float c[2][8][4];
    gemm_body(g_oh, g_wo, m0, n0, sA, sB, c);

    const int tid = threadIdx.x;
    const int w = tid >> 5, lane = tid & 31;
    const int gid = lane >> 2, tig = lane & 3;
#pragma unroll
    for (int mt = 0; mt < 2; mt++)
#pragma unroll
        for (int r01 = 0; r01 < 2; r01++) {
            int m = m0 + 32 * w + 16 * mt + gid + 8 * r01;
            float* op = &outf[(size_t)m * D_MODEL + n0];
#pragma unroll
            for (int n = 0; n < 8; n++) {
                int d = n * 8 + 2 * tig;
                float2 v;
                v.x = c[mt][n][2 * r01 + 0] + bias[n0 + d];
                v.y = c[mt][n][2 * r01 + 1] + bias[n0 + d + 1];
                *(float2*)(op + d) = v;
            }
        }
}

// ===========================================================================
// mma.sync f16 flash attention, v4 (R13 geometry + cross-tile S pipelining):
//  - CTA = 128 queries, 4 warps x 32 rows (keeps 2x B-fragment reuse)
//  - S double-buffered across tiles: per iteration the code order is
//      MMA1(kt+1) ; softmax(kt) ; MMA2(kt)
//    in one barrier-free block, so MMA1's HMMAs execute while the softmax
//    ALU/MUFU chain issues — tensor pipe stays fed through softmax.
//  - Q A-fragments in registers; cp.async 3-stage K/V pipeline (48 KB)
// ===========================================================================
__global__ __launch_bounds__(128)
void attn_mma_kernel()
{
    __shared__ __half sKV[3][2][64 * 64];   // [stage][0=K,1=V][8KB]

    const int tid  = threadIdx.x;
    const int w    = tid >> 5;
    const int lane = tid & 31;
    const int gid  = lane >> 2;
    const int tig  = lane & 3;
    const int bh   = blockIdx.y;
    const int qt   = blockIdx.x;

    const __half* Qp = g_qh + (size_t)bh * T_SEQ * D_K + (size_t)qt * 128 * D_K;
    const __half* Kb = g_kh + (size_t)bh * T_SEQ * D_K;
    const __half* Vb = g_vh + (size_t)bh * T_SEQ * D_K;

    unsigned uK[3], uV[3];
#pragma unroll
    for (int st = 0; st < 3; st++) {
        uK[st] = smem_u32(sKV[st][0]);
        uV[st] = smem_u32(sKV[st][1]);
    }
    const int arow = tid >> 3, ach = tid & 7;

    // ---- Prologue: Q (128 rows) through stage-2 smem -> register A-frags ----
    {
        char* q2 = (char*)sKV[2];   // 16 KB region
#pragma unroll
        for (int i = 0; i < 8; i++) {
            int row = arow + 16 * i;
            *(uint4*)(q2 + swz(row, ach)) =
                *(const uint4*)(Qp + row * D_K + ach * 8);
        }
    }
    __syncthreads();
    unsigned qf[2][4][4];   // [mt][kk][frag]
    {
        unsigned bQ = uK[2];
#pragma unroll
        for (int kk = 0; kk < 4; kk++)
#pragma unroll
            for (int mt = 0; mt < 2; mt++) {
                int row = 32 * w + 16 * mt + (lane & 15);
                int ch  = 2 * kk + (lane >> 4);
                ldm_x4(bQ + swz(row, ch), qf[mt][kk][0], qf[mt][kk][1],
                       qf[mt][kk][2], qf[mt][kk][3]);
            }
    }
    // Stage 2 is first overwritten by the cp.async issued in iteration kt=0,
    // after that iteration's __syncthreads() — qf already in registers.

    // ---- Kick off pipeline: tiles 0 and 1 ----
#pragma unroll
    for (int p = 0; p < 2; p++) {
        const __half* Kp = Kb + (size_t)p * 64 * D_K;
        const __half* Vp = Vb + (size_t)p * 64 * D_K;
#pragma unroll
        for (int i = 0; i < 4; i++) {
            int row = arow + 16 * i;
            cp_async16(uK[p] + swz(row, ach), Kp + row * D_K + ach * 8);
            cp_async16(uV[p] + swz(row, ach), Vp + row * D_K + ach * 8);
        }
        CP_COMMIT();
    }

    float o[2][8][4];
#pragma unroll
    for (int mt = 0; mt < 2; mt++)
#pragma unroll
        for (int n = 0; n < 8; n++)
#pragma unroll
            for (int cc = 0; cc < 4; cc++) o[mt][n][cc] = 0.0f;
    float mrow[2][2] = {{-1e30f, -1e30f}, {-1e30f, -1e30f}};
    float lrow[2][2] = {{0.0f, 0.0f}, {0.0f, 0.0f}};

    float sbuf[2][2][8][4];   // S double buffer [pp][mt][n][cc]

    // ---- Pre-loop: S(0) = Q * K(0)^T ----
    CP_WAIT(1);            // tile 0 arrived (tile 1 may be in flight)
    __syncthreads();
#pragma unroll
    for (int mt = 0; mt < 2; mt++)
#pragma unroll
        for (int n = 0; n < 8; n++)
#pragma unroll
            for (int cc = 0; cc < 4; cc++) sbuf[0][mt][n][cc] = 0.0f;
#pragma unroll
    for (int kk = 0; kk < 4; kk++) {
#pragma unroll
        for (int nt2 = 0; nt2 < 4; nt2++) {
            unsigned b0, b1, b2, b3;
            int row = nt2 * 16 + ((lane >> 4) << 3) + (lane & 7);
            int ch  = 2 * kk + ((lane >> 3) & 1);
            ldm_x4(uK[0] + swz(row, ch), b0, b1, b2, b3);
#pragma unroll
            for (int mt = 0; mt < 2; mt++) {
                mma16816(sbuf[0][mt][2 * nt2 + 0], qf[mt][kk], b0, b1);
                mma16816(sbuf[0][mt][2 * nt2 + 1], qf[mt][kk], b2, b3);
            }
        }
    }

    int cur = 0;
    for (int kt = 0; kt < NTILES; kt++) {
        // Tiles kt and kt+1 must be resident (MMA2 reads V(kt); MMA1 reads K(kt+1)).
        CP_WAIT(0);
        __syncthreads();   // cp data visible CTA-wide; all warps done with iter kt-1

        // Refill the stage retired at iteration kt-1 with tile kt+2.
        if (kt + 2 < NTILES) {
            const int st2 = (kt + 2) % 3;
            const __half* Kp = Kb + (size_t)(kt + 2) * 64 * D_K;
            const __half* Vp = Vb + (size_t)(kt + 2) * 64 * D_K;
#pragma unroll
            for (int i = 0; i < 4; i++) {
                int row = arow + 16 * i;
                cp_async16(uK[st2] + swz(row, ach), Kp + row * D_K + ach * 8);
                cp_async16(uV[st2] + swz(row, ach), Vp + row * D_K + ach * 8);
            }
            CP_COMMIT();
        }

        // ---- MMA1(kt+1) into the other S buffer (independent of softmax) ----
        if (kt + 1 < NTILES) {
            const unsigned cKn = uK[(kt + 1) % 3];
            float (*sn)[8][4] = sbuf[cur ^ 1];
#pragma unroll
            for (int mt = 0; mt < 2; mt++)
#pragma unroll
                for (int n = 0; n < 8; n++)
#pragma unroll
                    for (int cc = 0; cc < 4; cc++) sn[mt][n][cc] = 0.0f;
#pragma unroll
            for (int kk = 0; kk < 4; kk++) {
#pragma unroll
                for (int nt2 = 0; nt2 < 4; nt2++) {
                    unsigned b0, b1, b2, b3;
                    int row = nt2 * 16 + ((lane >> 4) << 3) + (lane & 7);
                    int ch  = 2 * kk + ((lane >> 3) & 1);
                    ldm_x4(cKn + swz(row, ch), b0, b1, b2, b3);
#pragma unroll
                    for (int mt = 0; mt < 2; mt++) {
                        mma16816(sn[mt][2 * nt2 + 0], qf[mt][kk], b0, b1);
                        mma16816(sn[mt][2 * nt2 + 1], qf[mt][kk], b2, b3);
                    }
                }
            }
        }

        // ---- Softmax on S(kt) (overlaps with MMA1's in-flight HMMAs) ----
        float (*s)[8][4] = sbuf[cur];
        unsigned pa_lo[2][8], pa_hi[2][8];
#pragma unroll
        for (int mt = 0; mt < 2; mt++) {
            float mx0 = -1e30f, mx1 = -1e30f;
#pragma unroll
            for (int n = 0; n < 8; n++) {
                mx0 = fmaxf(mx0, fmaxf(s[mt][n][0], s[mt][n][1]));
                mx1 = fmaxf(mx1, fmaxf(s[mt][n][2], s[mt][n][3]));
            }
            mx0 = fmaxf(mx0, __shfl_xor_sync(0xffffffffu, mx0, 1));
            mx0 = fmaxf(mx0, __shfl_xor_sync(0xffffffffu, mx0, 2));
            mx1 = fmaxf(mx1, __shfl_xor_sync(0xffffffffu, mx1, 1));
            mx1 = fmaxf(mx1, __shfl_xor_sync(0xffffffffu, mx1, 2));

            float m0n = fmaxf(mrow[mt][0], mx0);
            float m1n = fmaxf(mrow[mt][1], mx1);
            float c0 = fast_exp2(mrow[mt][0] - m0n);
            float c1 = fast_exp2(mrow[mt][1] - m1n);
            mrow[mt][0] = m0n;
            mrow[mt][1] = m1n;

            float sum0 = 0.0f, sum1 = 0.0f;
#pragma unroll
            for (int n = 0; n < 8; n++) {
                float p0 = fast_exp2(s[mt][n][0] - m0n);
                float p1 = fast_exp2(s[mt][n][1] - m0n);
                float p2 = fast_exp2(s[mt][n][2] - m1n);
                float p3 = fast_exp2(s[mt][n][3] - m1n);
                sum0 += p0 + p1;
                sum1 += p2 + p3;
                __half2 lo = __floats2half2_rn(p0, p1);
                __half2 hi = __floats2half2_rn(p2, p3);
                pa_lo[mt][n] = *reinterpret_cast<unsigned*>(&lo);
                pa_hi[mt][n] = *reinterpret_cast<unsigned*>(&hi);
            }
            sum0 += __shfl_xor_sync(0xffffffffu, sum0, 1);
            sum0 += __shfl_xor_sync(0xffffffffu, sum0, 2);
            sum1 += __shfl_xor_sync(0xffffffffu, sum1, 1);
            sum1 += __shfl_xor_sync(0xffffffffu, sum1, 2);
            lrow[mt][0] = lrow[mt][0] * c0 + sum0;
            lrow[mt][1] = lrow[mt][1] * c1 + sum1;

#pragma unroll
            for (int n = 0; n < 8; n++) {
                o[mt][n][0] *= c0;
                o[mt][n][1] *= c0;
                o[mt][n][2] *= c1;
                o[mt][n][3] *= c1;
            }
        }

        // ---- MMA2: O += P(kt) * V(kt) ----
        const unsigned cV = uV[kt % 3];
#pragma unroll
        for (int kk = 0; kk < 4; kk++) {
            unsigned aP[2][4];
#pragma unroll
            for (int mt = 0; mt < 2; mt++) {
                aP[mt][0] = pa_lo[mt][2 * kk];
                aP[mt][1] = pa_hi[mt][2 * kk];
                aP[mt][2] = pa_lo[mt][2 * kk + 1];
                aP[mt][3] = pa_hi[mt][2 * kk + 1];
            }
#pragma unroll
            for (int j2 = 0; j2 < 4; j2++) {
                unsigned b0, b1, b2, b3;
                int row = kk * 16 + (((lane >> 3) & 1) << 3) + (lane & 7);
                int ch  = 2 * j2 + (lane >> 4);
                ldm_x4_t(cV + swz(row, ch), b0, b1, b2, b3);
#pragma unroll
                for (int mt = 0; mt < 2; mt++) {
                    mma16816(o[mt][2 * j2 + 0], aP[mt], b0, b1);
                    mma16816(o[mt][2 * j2 + 1], aP[mt], b2, b3);
                }
            }
        }

        cur ^= 1;
    }

    // ---- Epilogue: normalize, write f16 to g_oh[(b*T + t)*512 + h*64 + d] ----
    const int b = bh >> 3;
    const int h = bh & 7;
#pragma unroll
    for (int mt = 0; mt < 2; mt++) {
#pragma unroll
        for (int r01 = 0; r01 < 2; r01++) {
            int t = qt * 128 + 32 * w + 16 * mt + gid + 8 * r01;
            float inv = 1.0f / lrow[mt][r01];
            __half* op = &g_oh[((size_t)(b * T_SEQ + t)) * D_MODEL + h * D_K];
#pragma unroll
            for (int n = 0; n < 8; n++) {
                __half2 hv = __floats2half2_rn(o[mt][n][2 * r01 + 0] * inv,
                                               o[mt][n][2 * r01 + 1] * inv);
                *(__half2*)(op + n * 8 + 2 * tig) = hv;
            }
        }
    }
}

// ===========================================================================
// Launch
// ===========================================================================
extern "C" void kernel_launch(void* const* d_in, const int* in_sizes, int n_in,
                              void* d_out, int out_size)
{
    const float* x  = (const float*)d_in[0];
    const float* Wq = (const float*)d_in[1];
    const float* bq = (const float*)d_in[2];
    const float* Wk = (const float*)d_in[3];
    const float* bk = (const float*)d_in[4];
    const float* Wv = (const float*)d_in[5];
    const float* bv = (const float*)d_in[6];
    const float* Wo = (const float*)d_in[7];
    const float* bo = (const float*)d_in[8];
    float* out = (float*)d_out;

    f2h_x_kernel<<<512, 256>>>(x, (M_ROWS * D_MODEL) / 4);
    f2h_w_kernel<<<dim3(64, 4, 1), 256>>>(Wq, Wk, Wv, Wo);

    dim3 blk(128, 1, 1);
    gemm_qkv_kernel<<<dim3(D_MODEL / 64, M_ROWS / 128, 3), blk>>>(bq, bk, bv);

    attn_mma_kernel<<<dim3(T_SEQ / 128, BH, 1), blk>>>();

    gemm_o_kernel<<<dim3(D_MODEL / 64, M_ROWS / 128, 1), blk>>>(bo, out);
}

// round 17
// speedup vs baseline: 1.4889x; 1.4730x over previous
#include <cuda_runtime.h>
#include <cuda_fp16.h>

// Problem constants
#define T_SEQ   4096
#define D_MODEL 512
#define N_HEADS 8
#define D_K     64
#define BATCH   2
#define BH      (BATCH * N_HEADS)       // 16
#define M_ROWS  (BATCH * T_SEQ)         // 8192
#define NTILES  (T_SEQ / 64)            // 64 key tiles

// Q is pre-scaled by 0.125 * log2(e) so softmax runs in base-2 domain.
#define QSCALE  (0.125f * 1.44269504088896f)
#define ONES_H2 0x3C003C00u             // packed f16 {1.0, 1.0}

// f16 intermediates (16B aligned for uint4 access)
__device__ __align__(16) __half g_xh[(size_t)M_ROWS * D_MODEL];    // x f16
__device__ __align__(16) __half g_wq[(size_t)D_MODEL * D_MODEL];
__device__ __align__(16) __half g_wk[(size_t)D_MODEL * D_MODEL];
__device__ __align__(16) __half g_wv[(size_t)D_MODEL * D_MODEL];
__device__ __align__(16) __half g_wo[(size_t)D_MODEL * D_MODEL];
__device__ __align__(16) __half g_qh[(size_t)BH * T_SEQ * D_K];    // [bh][t][64] (pre-scaled)
__device__ __align__(16) __half g_kh[(size_t)BH * T_SEQ * D_K];
__device__ __align__(16) __half g_vh[(size_t)BH * T_SEQ * D_K];
__device__ __align__(16) __half g_oh[(size_t)M_ROWS * D_MODEL];    // attention out f16

// ===========================================================================
// Small helpers
// ===========================================================================
__device__ __forceinline__ unsigned smem_u32(const void* p) {
    unsigned a;
    asm("{ .reg .u64 t; cvta.to.shared.u64 t, %1; cvt.u32.u64 %0, t; }" : "=r"(a) : "l"(p));
    return a;
}
__device__ __forceinline__ float fast_exp2(float x) {
    float y;
    asm("ex2.approx.ftz.f32 %0, %1;" : "=f"(y) : "f"(x));
    return y;
}
// Packed f16x2 exp2: one MUFU op for two values, result already A-frag packed.
__device__ __forceinline__ unsigned hex2(unsigned x) {
    unsigned y;
    asm("ex2.approx.f16x2 %0, %1;" : "=r"(y) : "r"(x));
    return y;
}
// Row-major [row][64 halfs] tile with XOR swizzle on 16B chunks:
// byte offset of (row, chunk) = row*128 + (chunk ^ (row&7))*16
__device__ __forceinline__ unsigned swz(int row, int ch) {
    return (unsigned)(row * 128 + ((ch ^ (row & 7)) << 4));
}
__device__ __forceinline__ void ldm_x4(unsigned addr, unsigned& r0, unsigned& r1,
                                       unsigned& r2, unsigned& r3) {
    asm volatile("ldmatrix.sync.aligned.m8n8.x4.shared.b16 {%0,%1,%2,%3}, [%4];"
                 : "=r"(r0), "=r"(r1), "=r"(r2), "=r"(r3) : "r"(addr));
}
__device__ __forceinline__ void ldm_x4_t(unsigned addr, unsigned& r0, unsigned& r1,
                                         unsigned& r2, unsigned& r3) {
    asm volatile("ldmatrix.sync.aligned.m8n8.x4.trans.shared.b16 {%0,%1,%2,%3}, [%4];"
                 : "=r"(r0), "=r"(r1), "=r"(r2), "=r"(r3) : "r"(addr));
}
__device__ __forceinline__ void mma16816(float* c, const unsigned* a,
                                         unsigned b0, unsigned b1) {
    asm volatile(
        "mma.sync.aligned.m16n8k16.row.col.f32.f16.f16.f32 "
        "{%0,%1,%2,%3}, {%4,%5,%6,%7}, {%8,%9}, {%0,%1,%2,%3};"
        : "+f"(c[0]), "+f"(c[1]), "+f"(c[2]), "+f"(c[3])
        : "r"(a[0]), "r"(a[1]), "r"(a[2]), "r"(a[3]), "r"(b0), "r"(b1));
}
__device__ __forceinline__ void cp_async16(unsigned dst, const void* src) {
    asm volatile("cp.async.cg.shared.global [%0], [%1], 16;" :: "r"(dst), "l"(src));
}
#define CP_COMMIT()  asm volatile("cp.async.commit_group;" ::: "memory")
#define CP_WAIT(n)   asm volatile("cp.async.wait_group %0;" :: "n"(n) : "memory")

// ===========================================================================
// fp32 -> f16 converts.
// ===========================================================================
__global__ __launch_bounds__(256)
void f2h_x_kernel(const float* __restrict__ src, int n4)
{
    for (int i = blockIdx.x * blockDim.x + threadIdx.x; i < n4;
         i += gridDim.x * blockDim.x) {
        float4 v = *(const float4*)(src + 4 * (size_t)i);
        __half2 lo = __floats2half2_rn(v.x, v.y);
        __half2 hi = __floats2half2_rn(v.z, v.w);
        uint2 pk;
        pk.x = *reinterpret_cast<unsigned*>(&lo);
        pk.y = *reinterpret_cast<unsigned*>(&hi);
        *(uint2*)(g_xh + 4 * (size_t)i) = pk;
    }
}
__global__ __launch_bounds__(256)
void f2h_w_kernel(const float* __restrict__ wq, const float* __restrict__ wk,
                  const float* __restrict__ wv, const float* __restrict__ wo)
{
    const int sel = blockIdx.y;
    const float* src = (sel == 0) ? wq : (sel == 1) ? wk : (sel == 2) ? wv : wo;
    __half* dst = (sel == 0) ? g_wq : (sel == 1) ? g_wk : (sel == 2) ? g_wv : g_wo;
    const int n4 = (D_MODEL * D_MODEL) / 4;
    for (int i = blockIdx.x * blockDim.x + threadIdx.x; i < n4;
         i += gridDim.x * blockDim.x) {
        float4 v = *(const float4*)(src + 4 * (size_t)i);
        __half2 lo = __floats2half2_rn(v.x, v.y);
        __half2 hi = __floats2half2_rn(v.z, v.w);
        uint2 pk;
        pk.x = *reinterpret_cast<unsigned*>(&lo);
        pk.y = *reinterpret_cast<unsigned*>(&hi);
        *(uint2*)(dst + 4 * (size_t)i) = pk;
    }
}

// ===========================================================================
// f16 tensor-core GEMM body: C[m,n] = sum_k A[m,k]*W[n,k], fp32 accum.
// CTA tile 128m x 64n, K-chunks of 64, 4 warps.
// ===========================================================================
__device__ __forceinline__ void gemm_body(const __half* __restrict__ A,
                                          const __half* __restrict__ W,
                                          int m0, int n0,
                                          __half (*sA)[128 * 64], __half (*sB)[64 * 64],
                                          float c[2][8][4])
{
    const int tid  = threadIdx.x;
    const int w    = tid >> 5;
    const int lane = tid & 31;
    const unsigned bA0 = smem_u32(sA[0]), bA1 = smem_u32(sA[1]);
    const unsigned bB0 = smem_u32(sB[0]), bB1 = smem_u32(sB[1]);
    const int arow = tid >> 3, ach = tid & 7;

#pragma unroll
    for (int i = 0; i < 8; i++) {
        int row = arow + 16 * i;
        *(uint4*)((char*)sA[0] + swz(row, ach)) =
            *(const uint4*)(A + (size_t)(m0 + row) * D_MODEL + ach * 8);
    }
#pragma unroll
    for (int i = 0; i < 4; i++) {
        int row = arow + 16 * i;
        *(uint4*)((char*)sB[0] + swz(row, ach)) =
            *(const uint4*)(W + (size_t)(n0 + row) * D_MODEL + ach * 8);
    }
    __syncthreads();

#pragma unroll
    for (int mt = 0; mt < 2; mt++)
#pragma unroll
        for (int n = 0; n < 8; n++)
#pragma unroll
            for (int cc = 0; cc < 4; cc++) c[mt][n][cc] = 0.0f;

    for (int kt = 0; kt < D_MODEL / 64; kt++) {
        const int cur = kt & 1;
        const unsigned cA = cur ? bA1 : bA0;
        const unsigned cB = cur ? bB1 : bB0;

        uint4 pA[8], pB[4];
        if (kt + 1 < D_MODEL / 64) {
            const __half* Ap = A + (size_t)(kt + 1) * 64;
            const __half* Wp = W + (size_t)(kt + 1) * 64;
#pragma unroll
            for (int i = 0; i < 8; i++) {
                int row = arow + 16 * i;
                pA[i] = *(const uint4*)(Ap + (size_t)(m0 + row) * D_MODEL + ach * 8);
            }
#pragma unroll
            for (int i = 0; i < 4; i++) {
                int row = arow + 16 * i;
                pB[i] = *(const uint4*)(Wp + (size_t)(n0 + row) * D_MODEL + ach * 8);
            }
        }

#pragma unroll
        for (int kk = 0; kk < 4; kk++) {
            unsigned a[2][4];
#pragma unroll
            for (int mt = 0; mt < 2; mt++) {
                int row = 32 * w + 16 * mt + (lane & 15);
                int ch  = 2 * kk + (lane >> 4);
                ldm_x4(cA + swz(row, ch), a[mt][0], a[mt][1], a[mt][2], a[mt][3]);
            }
#pragma unroll
            for (int nt2 = 0; nt2 < 4; nt2++) {
                unsigned b0, b1, b2, b3;
                int row = nt2 * 16 + ((lane >> 4) << 3) + (lane & 7);
                int ch  = 2 * kk + ((lane >> 3) & 1);
                ldm_x4(cB + swz(row, ch), b0, b1, b2, b3);
#pragma unroll
                for (int mt = 0; mt < 2; mt++) {
                    mma16816(c[mt][2 * nt2 + 0], a[mt], b0, b1);
                    mma16816(c[mt][2 * nt2 + 1], a[mt], b2, b3);
                }
            }
        }

        if (kt + 1 < D_MODEL / 64) {
            __half* nA = (__half*)(cur ? (void*)sA[0] : (void*)sA[1]);
            __half* nB = (__half*)(cur ? (void*)sB[0] : (void*)sB[1]);
#pragma unroll
            for (int i = 0; i < 8; i++)
                *(uint4*)((char*)nA + swz(arow + 16 * i, ach)) = pA[i];
#pragma unroll
            for (int i = 0; i < 4; i++)
                *(uint4*)((char*)nB + swz(arow + 16 * i, ach)) = pB[i];
        }
        __syncthreads();
    }
}

// QKV projections fused: blockIdx.z = 0(Q)/1(K)/2(V).
__global__ __launch_bounds__(128)
void gemm_qkv_kernel(const float* __restrict__ bq, const float* __restrict__ bk,
                     const float* __restrict__ bv)
{
    __shared__ __half sA[2][128 * 64];
    __shared__ __half sB[2][64 * 64];

    const int z = blockIdx.z;
    const __half* W = (z == 0) ? g_wq : (z == 1) ? g_wk : g_wv;
    const float* bias = (z == 0) ? bq : (z == 1) ? bk : bv;
    __half* dst = (z == 0) ? g_qh : (z == 1) ? g_kh : g_vh;
    const float sc = (z == 0) ? QSCALE : 1.0f;

    const int n0 = blockIdx.x * 64;
    const int m0 = blockIdx.y * 128;
    const int h  = blockIdx.x;

    float c[2][8][4];
    gemm_body(g_xh, W, m0, n0, sA, sB, c);

    const int tid = threadIdx.x;
    const int w = tid >> 5, lane = tid & 31;
    const int gid = lane >> 2, tig = lane & 3;
#pragma unroll
    for (int mt = 0; mt < 2; mt++)
#pragma unroll
        for (int r01 = 0; r01 < 2; r01++) {
            int m = m0 + 32 * w + 16 * mt + gid + 8 * r01;
            int b = m >> 12;
            int t = m & (T_SEQ - 1);
            __half* op = &dst[(((size_t)(b * N_HEADS + h)) * T_SEQ + t) * D_K];
#pragma unroll
            for (int n = 0; n < 8; n++) {
                int d = n * 8 + 2 * tig;
                __half2 hv = __floats2half2_rn(
                    (c[mt][n][2 * r01 + 0] + bias[n0 + d]) * sc,
                    (c[mt][n][2 * r01 + 1] + bias[n0 + d + 1]) * sc);
                *(__half2*)(op + d) = hv;
            }
        }
}

// Output projection: A = g_oh, fp32 result to out.
__global__ __launch_bounds__(128)
void gemm_o_kernel(const float* __restrict__ bias, float* __restrict__ outf)
{
    __shared__ __half sA[2][128 * 64];
    __shared__ __half sB[2][64 * 64];

    const int n0 = blockIdx.x * 64;
    const int m0 = blockIdx.y * 128;

    float c[2][8][4];
    gemm_body(g_oh, g_wo, m0, n0, sA, sB, c);

    const int tid = threadIdx.x;
    const int w = tid >> 5, lane = tid & 31;
    const int gid = lane >> 2, tig = lane & 3;
#pragma unroll
    for (int mt = 0; mt < 2; mt++)
#pragma unroll
        for (int r01 = 0; r01 < 2; r01++) {
            int m = m0 + 32 * w + 16 * mt + gid + 8 * r01;
            float* op = &outf[(size_t)m * D_MODEL + n0];
#pragma unroll
            for (int n = 0; n < 8; n++) {
                int d = n * 8 + 2 * tig;
                float2 v;
                v.x = c[mt][n][2 * r01 + 0] + bias[n0 + d];
                v.y = c[mt][n][2 * r01 + 1] + bias[n0 + d + 1];
                *(float2*)(op + d) = v;
            }
        }
}

// ===========================================================================
// mma.sync f16 flash attention, v5 = R13 base + cheap softmax:
//  - CTA = 128 queries, 4 warps x 32 rows; cp.async 3-stage K/V; Q in regs
//  - exponentials via ex2.approx.f16x2: half the MUFU ops, result lands
//    pre-packed as MMA2 A-fragments
//  - row sums via ones-MMA (B frags = packed f16 1.0): kills the fp32 sum
//    chains and all sum shuffles; lrow is consistent with O (same f16 P)
// ===========================================================================
__global__ __launch_bounds__(128)
void attn_mma_kernel()
{
    __shared__ __half sKV[3][2][64 * 64];   // [stage][0=K,1=V][8KB]

    const int tid  = threadIdx.x;
    const int w    = tid >> 5;
    const int lane = tid & 31;
    const int gid  = lane >> 2;
    const int tig  = lane & 3;
    const int bh   = blockIdx.y;
    const int qt   = blockIdx.x;

    const __half* Qp = g_qh + (size_t)bh * T_SEQ * D_K + (size_t)qt * 128 * D_K;
    const __half* Kb = g_kh + (size_t)bh * T_SEQ * D_K;
    const __half* Vb = g_vh + (size_t)bh * T_SEQ * D_K;

    unsigned uK[3], uV[3];
#pragma unroll
    for (int st = 0; st < 3; st++) {
        uK[st] = smem_u32(sKV[st][0]);
        uV[st] = smem_u32(sKV[st][1]);
    }
    const int arow = tid >> 3, ach = tid & 7;

    // ---- Prologue: Q (128 rows) through stage-2 smem -> register A-frags ----
    {
        char* q2 = (char*)sKV[2];
#pragma unroll
        for (int i = 0; i < 8; i++) {
            int row = arow + 16 * i;
            *(uint4*)(q2 + swz(row, ach)) =
                *(const uint4*)(Qp + row * D_K + ach * 8);
        }
    }
    __syncthreads();
    unsigned qf[2][4][4];   // [mt][kk][frag]
    {
        unsigned bQ = uK[2];
#pragma unroll
        for (int kk = 0; kk < 4; kk++)
#pragma unroll
            for (int mt = 0; mt < 2; mt++) {
                int row = 32 * w + 16 * mt + (lane & 15);
                int ch  = 2 * kk + (lane >> 4);
                ldm_x4(bQ + swz(row, ch), qf[mt][kk][0], qf[mt][kk][1],
                       qf[mt][kk][2], qf[mt][kk][3]);
            }
    }
    // Stage 2 is first overwritten by the cp.async issued in iteration kt=0,
    // after that iteration's __syncthreads() — qf already in registers.

    // ---- Kick off pipeline: tiles 0 and 1 ----
#pragma unroll
    for (int p = 0; p < 2; p++) {
        const __half* Kp = Kb + (size_t)p * 64 * D_K;
        const __half* Vp = Vb + (size_t)p * 64 * D_K;
#pragma unroll
        for (int i = 0; i < 4; i++) {
            int row = arow + 16 * i;
            cp_async16(uK[p] + swz(row, ach), Kp + row * D_K + ach * 8);
            cp_async16(uV[p] + swz(row, ach), Vp + row * D_K + ach * 8);
        }
        CP_COMMIT();
    }

    float o[2][8][4];
#pragma unroll
    for (int mt = 0; mt < 2; mt++)
#pragma unroll
        for (int n = 0; n < 8; n++)
#pragma unroll
            for (int cc = 0; cc < 4; cc++) o[mt][n][cc] = 0.0f;
    float mrow[2][2] = {{-1e30f, -1e30f}, {-1e30f, -1e30f}};
    float lrow[2][2] = {{0.0f, 0.0f}, {0.0f, 0.0f}};

    for (int kt = 0; kt < NTILES; kt++) {
        const int st = kt % 3;
        const unsigned cK = uK[st];
        const unsigned cV = uV[st];

        if (kt + 1 < NTILES) { CP_WAIT(1); } else { CP_WAIT(0); }
        __syncthreads();

        if (kt + 2 < NTILES) {
            const int st2 = (kt + 2) % 3;
            const __half* Kp = Kb + (size_t)(kt + 2) * 64 * D_K;
            const __half* Vp = Vb + (size_t)(kt + 2) * 64 * D_K;
#pragma unroll
            for (int i = 0; i < 4; i++) {
                int row = arow + 16 * i;
                cp_async16(uK[st2] + swz(row, ach), Kp + row * D_K + ach * 8);
                cp_async16(uV[st2] + swz(row, ach), Vp + row * D_K + ach * 8);
            }
            CP_COMMIT();
        }

        // ---- MMA1: S = Q * K^T (Q frags from registers) ----
        float s[2][8][4];
#pragma unroll
        for (int mt = 0; mt < 2; mt++)
#pragma unroll
            for (int n = 0; n < 8; n++)
#pragma unroll
                for (int cc = 0; cc < 4; cc++) s[mt][n][cc] = 0.0f;

#pragma unroll
        for (int kk = 0; kk < 4; kk++) {
#pragma unroll
            for (int nt2 = 0; nt2 < 4; nt2++) {
                unsigned b0, b1, b2, b3;
                int row = nt2 * 16 + ((lane >> 4) << 3) + (lane & 7);
                int ch  = 2 * kk + ((lane >> 3) & 1);
                ldm_x4(cK + swz(row, ch), b0, b1, b2, b3);
#pragma unroll
                for (int mt = 0; mt < 2; mt++) {
                    mma16816(s[mt][2 * nt2 + 0], qf[mt][kk], b0, b1);
                    mma16816(s[mt][2 * nt2 + 1], qf[mt][kk], b2, b3);
                }
            }
        }

        // ---- Online softmax (base-2; f16x2 exp; sums deferred to ones-MMA) ----
        unsigned pa_lo[2][8], pa_hi[2][8];
        float corr0[2], corr1[2];
#pragma unroll
        for (int mt = 0; mt < 2; mt++) {
            float mx0 = -1e30f, mx1 = -1e30f;
#pragma unroll
            for (int n = 0; n < 8; n++) {
                mx0 = fmaxf(mx0, fmaxf(s[mt][n][0], s[mt][n][1]));
                mx1 = fmaxf(mx1, fmaxf(s[mt][n][2], s[mt][n][3]));
            }
            mx0 = fmaxf(mx0, __shfl_xor_sync(0xffffffffu, mx0, 1));
            mx0 = fmaxf(mx0, __shfl_xor_sync(0xffffffffu, mx0, 2));
            mx1 = fmaxf(mx1, __shfl_xor_sync(0xffffffffu, mx1, 1));
            mx1 = fmaxf(mx1, __shfl_xor_sync(0xffffffffu, mx1, 2));

            float m0n = fmaxf(mrow[mt][0], mx0);
            float m1n = fmaxf(mrow[mt][1], mx1);
            corr0[mt] = fast_exp2(mrow[mt][0] - m0n);
            corr1[mt] = fast_exp2(mrow[mt][1] - m1n);
            mrow[mt][0] = m0n;
            mrow[mt][1] = m1n;

#pragma unroll
            for (int n = 0; n < 8; n++) {
                __half2 hlo = __floats2half2_rn(s[mt][n][0] - m0n, s[mt][n][1] - m0n);
                __half2 hhi = __floats2half2_rn(s[mt][n][2] - m1n, s[mt][n][3] - m1n);
                pa_lo[mt][n] = hex2(*reinterpret_cast<unsigned*>(&hlo));
                pa_hi[mt][n] = hex2(*reinterpret_cast<unsigned*>(&hhi));
            }

#pragma unroll
            for (int n = 0; n < 8; n++) {
                o[mt][n][0] *= corr0[mt];
                o[mt][n][1] *= corr0[mt];
                o[mt][n][2] *= corr1[mt];
                o[mt][n][3] *= corr1[mt];
            }
        }

        // ---- MMA2: O += P * V, and rowsum(P) via ones-MMA ----
        float ls[2][4];
#pragma unroll
        for (int mt = 0; mt < 2; mt++)
#pragma unroll
            for (int cc = 0; cc < 4; cc++) ls[mt][cc] = 0.0f;

#pragma unroll
        for (int kk = 0; kk < 4; kk++) {
            unsigned aP[2][4];
#pragma unroll
            for (int mt = 0; mt < 2; mt++) {
                aP[mt][0] = pa_lo[mt][2 * kk];
                aP[mt][1] = pa_hi[mt][2 * kk];
                aP[mt][2] = pa_lo[mt][2 * kk + 1];
                aP[mt][3] = pa_hi[mt][2 * kk + 1];
            }
#pragma unroll
            for (int j2 = 0; j2 < 4; j2++) {
                unsigned b0, b1, b2, b3;
                int row = kk * 16 + (((lane >> 3) & 1) << 3) + (lane & 7);
                int ch  = 2 * j2 + (lane >> 4);
                ldm_x4_t(cV + swz(row, ch), b0, b1, b2, b3);
#pragma unroll
                for (int mt = 0; mt < 2; mt++) {
                    mma16816(o[mt][2 * j2 + 0], aP[mt], b0, b1);
                    mma16816(o[mt][2 * j2 + 1], aP[mt], b2, b3);
                }
            }
            // rowsum: every output column of (P x ones) equals the row sum
#pragma unroll
            for (int mt = 0; mt < 2; mt++)
                mma16816(ls[mt], aP[mt], ONES_H2, ONES_H2);
        }

#pragma unroll
        for (int mt = 0; mt < 2; mt++) {
            lrow[mt][0] = lrow[mt][0] * corr0[mt] + ls[mt][0];
            lrow[mt][1] = lrow[mt][1] * corr1[mt] + ls[mt][2];
        }
    }

    // ---- Epilogue: normalize, write f16 to g_oh[(b*T + t)*512 + h*64 + d] ----
    const int b = bh >> 3;
    const int h = bh & 7;
#pragma unroll
    for (int mt = 0; mt < 2; mt++) {
#pragma unroll
        for (int r01 = 0; r01 < 2; r01++) {
            int t = qt * 128 + 32 * w + 16 * mt + gid + 8 * r01;
            float inv = 1.0f / lrow[mt][r01];
            __half* op = &g_oh[((size_t)(b * T_SEQ + t)) * D_MODEL + h * D_K];
#pragma unroll
            for (int n = 0; n < 8; n++) {
                __half2 hv = __floats2half2_rn(o[mt][n][2 * r01 + 0] * inv,
                                               o[mt][n][2 * r01 + 1] * inv);
                *(__half2*)(op + n * 8 + 2 * tig) = hv;
            }
        }
    }
}

// ===========================================================================
// Launch
// ===========================================================================
extern "C" void kernel_launch(void* const* d_in, const int* in_sizes, int n_in,
                              void* d_out, int out_size)
{
    const float* x  = (const float*)d_in[0];
    const float* Wq = (const float*)d_in[1];
    const float* bq = (const float*)d_in[2];
    const float* Wk = (const float*)d_in[3];
    const float* bk = (const float*)d_in[4];
    const float* Wv = (const float*)d_in[5];
    const float* bv = (const float*)d_in[6];
    const float* Wo = (const float*)d_in[7];
    const float* bo = (const float*)d_in[8];
    float* out = (float*)d_out;

    f2h_x_kernel<<<512, 256>>>(x, (M_ROWS * D_MODEL) / 4);
    f2h_w_kernel<<<dim3(64, 4, 1), 256>>>(Wq, Wk, Wv, Wo);

    dim3 blk(128, 1, 1);
    gemm_qkv_kernel<<<dim3(D_MODEL / 64, M_ROWS / 128, 3), blk>>>(bq, bk, bv);

    attn_mma_kernel<<<dim3(T_SEQ / 128, BH, 1), blk>>>();

    gemm_o_kernel<<<dim3(D_MODEL / 64, M_ROWS / 128, 1), blk>>>(bo, out);
}